// round 4
// baseline (speedup 1.0000x reference)
#include <cuda_runtime.h>
#include <cuda_bf16.h>
#include <mma.h>
#include <cstdint>

using namespace nvcuda;

// ============================================================================
// GridNeRF forward via warp-level bf16 mma.sync (HMMA), hi/lo split => ~fp32.
// Inputs: x, v, o, table, dw1, db1, dw2, db2, rw1, rb1, rw2, rb2
// Output: [sigma (N)] ++ [rgb (N*3)] float32.
//
// Per warp: 16 points.
//   L1: X[16,48]  @ W1[48,64]  -> relu -> H1
//   L2: H1[16,64] @ W2[64,80]  (col0 = sigma head, cols1..64 = feat)
//   L3: A3[16,80] @ W3[80,64]  (A3 = feat ++ SH ++ 0) -> relu -> H3
//   L4: H3[16,64] @ W4[64,16]  (cols 0..2 -> sigmoid -> rgb)
// Each GEMM: 3 accumulating MMA passes (Ah*Bh + Al*Bh + Ah*Bl).
// ============================================================================

constexpr int TSZ = 1 << 19;
constexpr int WARPS = 12;              // per CTA
constexpr int LDA = 80;                // A-buf stride (bf16 elems)
constexpr int LDD = 80;                // D stage stride (fp32)

// prepped weights (bf16 row-major [K][N], hi then lo per layer) + biases
// elem offsets: W1h 0 (48x64) W1l 3072 | W2h 6144 (64x80) W2l 11264 |
//               W3h 16384 (80x64) W3l 21504 | W4h 26624 (64x16) W4l 27648
__device__ __align__(16) __nv_bfloat16 g_w[28672];
__device__ __align__(16) float g_b[224];   // b1@0[64] b2@64[80] b3@144[64] b4@208[16]

constexpr int oW1 = 0,    oW1l = 3072;
constexpr int oW2 = 6144, oW2l = 11264;
constexpr int oW3 = 16384, oW3l = 21504;
constexpr int oW4 = 26624, oW4l = 27648;

// ---------------- weight prep ----------------
__device__ __forceinline__ void splitw(int hi_off, int lo_off, int idx, float w) {
    __nv_bfloat16 h = __float2bfloat16(w);
    g_w[hi_off + idx] = h;
    g_w[lo_off + idx] = __float2bfloat16(w - __bfloat162float(h));
}

__global__ void prep_weights(const float* __restrict__ dw1, const float* __restrict__ db1,
                             const float* __restrict__ dw2, const float* __restrict__ db2,
                             const float* __restrict__ rw1, const float* __restrict__ rb1,
                             const float* __restrict__ rw2, const float* __restrict__ rb2)
{
    const int tid = threadIdx.x;  // 256
    for (int i = tid; i < 28672; i += 256) g_w[i] = __float2bfloat16(0.0f);
    for (int i = tid; i < 224; i += 256) g_b[i] = 0.0f;
    __syncthreads();
    // W1[48][64]: rows 0..46 = dw1
    for (int i = tid; i < 47 * 64; i += 256)
        splitw(oW1, oW1l, (i / 64) * 64 + (i % 64), dw1[i]);
    // W2[64][80]: cols 0..64 = dw2[m][j]
    for (int i = tid; i < 64 * 65; i += 256) {
        int m = i / 65, j = i % 65;
        splitw(oW2, oW2l, m * 80 + j, dw2[i]);
    }
    // W3[80][64]: rows 0..72 = rw1
    for (int i = tid; i < 73 * 64; i += 256)
        splitw(oW3, oW3l, i, rw1[i]);
    // W4[64][16]: cols 0..2 = rw2
    for (int i = tid; i < 64 * 3; i += 256) {
        int k = i / 3, c = i % 3;
        splitw(oW4, oW4l, k * 16 + c, rw2[i]);
    }
    for (int i = tid; i < 64; i += 256) g_b[i] = db1[i];
    for (int i = tid; i < 65; i += 256) g_b[64 + i] = db2[i];
    for (int i = tid; i < 64; i += 256) g_b[144 + i] = rb1[i];
    for (int i = tid; i < 3; i += 256) g_b[208 + i] = rb2[i];
}

// ---------------- per-warp GEMM: D = Ah*Wh + Al*Wh + Ah*Wl ----------------
template<int KT, int NT>
__device__ __forceinline__ void gemm_layer(
    const __nv_bfloat16* Ah, const __nv_bfloat16* Al,
    const __nv_bfloat16* Wh, const __nv_bfloat16* Wl, int ldb,
    float* Dst)
{
    wmma::fragment<wmma::matrix_a, 16, 16, 16, __nv_bfloat16, wmma::row_major> ah[KT], al[KT];
    #pragma unroll
    for (int k = 0; k < KT; k++) {
        wmma::load_matrix_sync(ah[k], Ah + k * 16, LDA);
        wmma::load_matrix_sync(al[k], Al + k * 16, LDA);
    }
    #pragma unroll
    for (int nn = 0; nn < NT; nn++) {
        wmma::fragment<wmma::accumulator, 16, 16, 16, float> acc;
        wmma::fill_fragment(acc, 0.0f);
        #pragma unroll
        for (int k = 0; k < KT; k++) {
            wmma::fragment<wmma::matrix_b, 16, 16, 16, __nv_bfloat16, wmma::row_major> bh, bl;
            wmma::load_matrix_sync(bh, Wh + k * 16 * ldb + nn * 16, ldb);
            wmma::mma_sync(acc, ah[k], bh, acc);
            wmma::mma_sync(acc, al[k], bh, acc);
            wmma::load_matrix_sync(bl, Wl + k * 16 * ldb + nn * 16, ldb);
            wmma::mma_sync(acc, ah[k], bl, acc);
        }
        wmma::store_matrix_sync(Dst + nn * 16, acc, LDD, wmma::mem_row_major);
    }
    __syncwarp();
}

__device__ __forceinline__ void put_a(__nv_bfloat16* Ah, __nv_bfloat16* Al,
                                      int row, int col, float w) {
    __nv_bfloat16 h = __float2bfloat16(w);
    Ah[row * LDA + col] = h;
    Al[row * LDA + col] = __float2bfloat16(w - __bfloat162float(h));
}

// ---------------- main kernel ----------------
// smem: weights 57344 B | biases 896 B | per warp: Ah 2560, Al 2560, D 5120
constexpr int oSW = 0, oSB = 57344, oWARP = 58240, WARP_BYTES = 10240;
constexpr int SMEM_DYN = oWARP + WARPS * WARP_BYTES;   // 181120

__global__ void __launch_bounds__(WARPS * 32, 1) nerf_mma(
    const float* __restrict__ x, const float* __restrict__ v,
    const float* __restrict__ table,
    float* __restrict__ out, int n)
{
    extern __shared__ __align__(16) unsigned char S[];
    __nv_bfloat16* sW = (__nv_bfloat16*)(S + oSW);
    float* sB = (float*)(S + oSB);

    const int tid = threadIdx.x;
    const int wid = tid >> 5, lane = tid & 31;

    // stage weights + biases
    for (int i = tid; i < 57344 / 16; i += WARPS * 32)
        ((uint4*)sW)[i] = ((const uint4*)g_w)[i];
    for (int i = tid; i < 224; i += WARPS * 32) sB[i] = g_b[i];
    __syncthreads();

    const int tile = blockIdx.x * WARPS + wid;
    const int ntiles = n >> 4;
    if (tile >= ntiles) return;

    unsigned char* WS = S + oWARP + wid * WARP_BYTES;
    __nv_bfloat16* Ah = (__nv_bfloat16*)WS;
    __nv_bfloat16* Al = (__nv_bfloat16*)(WS + 2560);
    float* D = (float*)(WS + 5120);

    const int row = lane >> 1;          // 0..15
    const int half = lane & 1;
    const int gp = tile * 16 + row;     // this lane-pair's point

    // ================= encoding -> A[16][48] =================
    {
        const float px0 = x[3 * gp + 0];
        const float px1 = x[3 * gp + 1];
        const float px2 = x[3 * gp + 2];
        if (half == 0) {
            put_a(Ah, Al, row, 0, px0);
            put_a(Ah, Al, row, 1, px1);
            put_a(Ah, Al, row, 2, px2);
            float pv[2] = {px0, px1};
            #pragma unroll
            for (int d = 0; d < 2; d++) {
                float fm = 1.0f;
                #pragma unroll
                for (int fr = 0; fr < 6; fr++) {
                    float s, c;
                    __sincosf(pv[d] * fm, &s, &c);
                    put_a(Ah, Al, row, 3 + d * 12 + fr, s);
                    put_a(Ah, Al, row, 3 + d * 12 + 6 + fr, c);
                    fm *= 2.0f;
                }
            }
        } else {
            float fm = 1.0f;
            #pragma unroll
            for (int fr = 0; fr < 6; fr++) {
                float s, c;
                __sincosf(px2 * fm, &s, &c);
                put_a(Ah, Al, row, 27 + fr, s);
                put_a(Ah, Al, row, 33 + fr, c);
                fm *= 2.0f;
            }
            const float x01x = (px0 + 1.0f) * 0.5f;
            const float x01y = (px1 + 1.0f) * 0.5f;
            const float x01z = (px2 + 1.0f) * 0.5f;
            const float resf[4] = {33.0f, 43.0f, 56.0f, 74.0f};
            #pragma unroll
            for (int lv = 0; lv < 4; lv++) {
                const float pxx = x01x * resf[lv], pyy = x01y * resf[lv], pzz = x01z * resf[lv];
                const float fx = floorf(pxx), fy = floorf(pyy), fz = floorf(pzz);
                const float tx = pxx - fx, ty = pyy - fy, tz = pzz - fz;
                const float wx = tx * tx * (3.0f - 2.0f * tx);
                const float wy = ty * ty * (3.0f - 2.0f * ty);
                const float wz = tz * tz * (3.0f - 2.0f * tz);
                const unsigned cx = (unsigned)fx, cy = (unsigned)fy, cz = (unsigned)fz;
                const float* tb = table + (size_t)lv * (TSZ * 2);
                float f0 = 0.0f, f1 = 0.0f;
                #pragma unroll
                for (int c = 0; c < 8; c++) {
                    const unsigned hx = cx + (c & 1);
                    const unsigned hy = cy + ((c >> 1) & 1);
                    const unsigned hz = cz + ((c >> 2) & 1);
                    const unsigned hsh = (hx ^ (hy * 2654435761u) ^ (hz * 805459861u)) & (unsigned)(TSZ - 1);
                    const float cw = ((c & 1) ? wx : 1.0f - wx)
                                   * (((c >> 1) & 1) ? wy : 1.0f - wy)
                                   * (((c >> 2) & 1) ? wz : 1.0f - wz);
                    const float2 tv = __ldg(reinterpret_cast<const float2*>(tb + 2u * hsh));
                    f0 = fmaf(tv.x, cw, f0);
                    f1 = fmaf(tv.y, cw, f1);
                }
                put_a(Ah, Al, row, 39 + 2 * lv, f0);
                put_a(Ah, Al, row, 40 + 2 * lv, f1);
            }
            put_a(Ah, Al, row, 47, 0.0f);
        }
    }
    __syncwarp();

    // ================= L1: [16,48]@[48,64] =================
    gemm_layer<3, 4>(Ah, Al, sW + oW1, sW + oW1l, 64, D);
    // E1: relu(D + b1) -> A
    {
        const int bc = half * 32;
        #pragma unroll
        for (int j = 0; j < 32; j++) {
            float dv = fmaxf(D[row * LDD + bc + j] + sB[bc + j], 0.0f);
            put_a(Ah, Al, row, bc + j, dv);
        }
    }
    __syncwarp();

    // ================= L2: [16,64]@[64,80] =================
    gemm_layer<4, 5>(Ah, Al, sW + oW2, sW + oW2l, 80, D);
    // E2: sigma (col0) -> out; feat cols 1..64 -> A cols 0..63; SH -> A cols 64..79
    {
        if (half == 0) {
            out[gp] = __expf(D[row * LDD + 0] + sB[64 + 0]);
            // SH
            const float vx = v[3 * gp + 0];
            const float vy = v[3 * gp + 1];
            const float vz = v[3 * gp + 2];
            float sh[9];
            sh[0] = 0.28209479177387814f;
            sh[1] = -0.4886025119029199f * vy;
            sh[2] =  0.4886025119029199f * vz;
            sh[3] = -0.4886025119029199f * vx;
            sh[4] =  1.0925484305920792f * vx * vy;
            sh[5] = -1.0925484305920792f * vy * vz;
            sh[6] =  0.9461746957575601f * vz * vz - 0.31539156525252005f;
            sh[7] = -1.0925484305920792f * vx * vz;
            sh[8] =  0.5462742152960396f * (vx * vx - vy * vy);
            #pragma unroll
            for (int q = 0; q < 9; q++) put_a(Ah, Al, row, 64 + q, sh[q]);
            #pragma unroll
            for (int q = 73; q < 80; q++) put_a(Ah, Al, row, q, 0.0f);
        }
        const int bc = half * 32;
        #pragma unroll
        for (int j = 0; j < 32; j++) {
            int dc = 1 + bc + j;   // D col
            float fv = fmaxf(D[row * LDD + dc] + sB[64 + dc], 0.0f);
            put_a(Ah, Al, row, bc + j, fv);
        }
    }
    __syncwarp();

    // ================= L3: [16,80]@[80,64] =================
    gemm_layer<5, 4>(Ah, Al, sW + oW3, sW + oW3l, 64, D);
    // E3: relu(D + b3) -> A
    {
        const int bc = half * 32;
        #pragma unroll
        for (int j = 0; j < 32; j++) {
            float dv = fmaxf(D[row * LDD + bc + j] + sB[144 + bc + j], 0.0f);
            put_a(Ah, Al, row, bc + j, dv);
        }
    }
    __syncwarp();

    // ================= L4: [16,64]@[64,16] =================
    gemm_layer<4, 1>(Ah, Al, sW + oW4, sW + oW4l, 16, D);
    // E4: rgb = sigmoid(D[0..2] + b4)
    if (half == 0) {
        #pragma unroll
        for (int c = 0; c < 3; c++) {
            float z = D[row * LDD + c] + sB[208 + c];
            out[n + 3 * gp + c] = 1.0f / (1.0f + __expf(-z));
        }
    }
}

extern "C" void kernel_launch(void* const* d_in, const int* in_sizes, int n_in,
                              void* d_out, int out_size)
{
    const float* x     = (const float*)d_in[0];
    const float* v     = (const float*)d_in[1];
    const float* table = (const float*)d_in[3];
    const float* dw1   = (const float*)d_in[4];
    const float* db1   = (const float*)d_in[5];
    const float* dw2   = (const float*)d_in[6];
    const float* db2   = (const float*)d_in[7];
    const float* rw1   = (const float*)d_in[8];
    const float* rb1   = (const float*)d_in[9];
    const float* rw2   = (const float*)d_in[10];
    const float* rb2   = (const float*)d_in[11];
    float* out = (float*)d_out;

    const int n = in_sizes[0] / 3;
    const int ntiles = n / 16;
    const int blocks = (ntiles + WARPS - 1) / WARPS;

    cudaFuncSetAttribute(nerf_mma, cudaFuncAttributeMaxDynamicSharedMemorySize, SMEM_DYN);

    prep_weights<<<1, 256>>>(dw1, db1, dw2, db2, rw1, rb1, rw2, rb2);
    nerf_mma<<<blocks, WARPS * 32, SMEM_DYN>>>(x, v, table, out, n);
}

// round 5
// speedup vs baseline: 4.8574x; 4.8574x over previous
#include <cuda_runtime.h>
#include <cuda_bf16.h>
#include <cstdint>

// ============================================================================
// GridNeRF forward: register-chained mma.sync.m16n8k16 (bf16 hi/lo => ~fp32).
// Per warp-tile: 16 points.
//   L1: A1[16,48] @ W1t  -> 8 n8-tiles  (bias folded: A col47=1, W row47=b1)
//   L2: H1[16,64] @ W2t  -> 9 n8-tiles  (cols0..63 feat perm, col64 sigma)
//   L3: A3[16,80] @ W3t  -> 8 n8-tiles  (A3 = feat ++ SH ++ 1(bias) ++ 0)
//   L4: H3[16,64] @ W4t  -> 1 n8-tile   (cols0..2 -> sigmoid rgb)
// 3 MMA passes per k-tile: Ah*Bh + Al*Bh + Ah*Bl.
// ============================================================================

constexpr int TSZ = 1 << 19;

// weight blob (bf16 elems), transposed [N][K], padded strides (bytes ≡ 16 mod 32)
constexpr int sW1 = 56, sW2 = 72, sW3 = 88, sW4 = 72;   // elem strides
constexpr int oW1h = 0;
constexpr int oW1l = oW1h + 64 * sW1;
constexpr int oW2h = oW1l + 64 * sW1;
constexpr int oW2l = oW2h + 72 * sW2;
constexpr int oW3h = oW2l + 72 * sW2;
constexpr int oW3l = oW3h + 64 * sW3;
constexpr int oW4h = oW3l + 64 * sW3;
constexpr int oW4l = oW4h + 8 * sW4;
constexpr int W_ELEMS = oW4l + 8 * sW4;                 // 29952 elems = 59904 B

__device__ __align__(16) __nv_bfloat16 g_w[W_ELEMS];
__device__ __align__(16) float g_b2[72];  // perm: [0..63]=db2[1..64], [64]=db2[0]
__device__ __align__(16) float g_b4[8];   // rb2[0..2], rest 0

// smem layout (bytes)
constexpr int oSB2B = 59904;
constexpr int oSB4B = 60192;
constexpr int oSTB  = 60224;              // per-warp staging: hi 2304 + lo 2304
constexpr int SMEM_DYN = oSTB + 8 * 4608; // 97088

// ---------------- PTX helpers ----------------
__device__ __forceinline__ uint32_t smem_u32(const void* p) {
    uint32_t a;
    asm("{ .reg .u64 t; cvta.to.shared.u64 t, %1; cvt.u32.u64 %0, t; }"
        : "=r"(a) : "l"(p));
    return a;
}
__device__ __forceinline__ void ldsm4(uint32_t* r, uint32_t addr) {
    asm volatile("ldmatrix.sync.aligned.m8n8.x4.shared.b16 {%0,%1,%2,%3}, [%4];"
        : "=r"(r[0]), "=r"(r[1]), "=r"(r[2]), "=r"(r[3]) : "r"(addr));
}
__device__ __forceinline__ void ldsm2(uint32_t& r0, uint32_t& r1, uint32_t addr) {
    asm volatile("ldmatrix.sync.aligned.m8n8.x2.shared.b16 {%0,%1}, [%2];"
        : "=r"(r0), "=r"(r1) : "r"(addr));
}
#define MMA4(c, a, b0_, b1_) \
    asm volatile("mma.sync.aligned.m16n8k16.row.col.f32.bf16.bf16.f32 " \
        "{%0,%1,%2,%3},{%4,%5,%6,%7},{%8,%9},{%0,%1,%2,%3};" \
        : "+f"((c)[0]), "+f"((c)[1]), "+f"((c)[2]), "+f"((c)[3]) \
        : "r"((a)[0]), "r"((a)[1]), "r"((a)[2]), "r"((a)[3]), "r"(b0_), "r"(b1_))

// 2 k-tiles (one ldmatrix.x4 pair): hh, lh on Bh; hl on Bl  (6 MMA, 2 LDSM)
__device__ __forceinline__ void pass2(float* c, const uint32_t (*ah)[4],
                                      const uint32_t (*al)[4], int kt0,
                                      uint32_t bh_addr, uint32_t bl_addr) {
    uint32_t bb[4];
    ldsm4(bb, bh_addr);
    MMA4(c, ah[kt0], bb[0], bb[1]);
    MMA4(c, ah[kt0 + 1], bb[2], bb[3]);
    MMA4(c, al[kt0], bb[0], bb[1]);
    MMA4(c, al[kt0 + 1], bb[2], bb[3]);
    ldsm4(bb, bl_addr);
    MMA4(c, ah[kt0], bb[0], bb[1]);
    MMA4(c, ah[kt0 + 1], bb[2], bb[3]);
}
// single k-tile (ldmatrix.x2): 3 MMA, 2 LDSM
__device__ __forceinline__ void pass1(float* c, const uint32_t* ah, const uint32_t* al,
                                      uint32_t bh_addr, uint32_t bl_addr) {
    uint32_t r0, r1;
    ldsm2(r0, r1, bh_addr);
    MMA4(c, ah, r0, r1);
    MMA4(c, al, r0, r1);
    ldsm2(r0, r1, bl_addr);
    MMA4(c, ah, r0, r1);
}

// relu + split fp32 pair -> bf16 hi (ret) and lo (out param)
__device__ __forceinline__ uint32_t bf2r(float a, float b, uint32_t& lo) {
    a = fmaxf(a, 0.0f); b = fmaxf(b, 0.0f);
    __nv_bfloat162 h = __floats2bfloat162_rn(a, b);
    __nv_bfloat162 l = __floats2bfloat162_rn(a - __bfloat162float(h.x),
                                             b - __bfloat162float(h.y));
    lo = *reinterpret_cast<uint32_t*>(&l);
    return *reinterpret_cast<uint32_t*>(&h);
}

// ---------------- weight prep ----------------
__device__ __forceinline__ void put_w(int hi, int lo, float w) {
    __nv_bfloat16 h = __float2bfloat16(w);
    g_w[hi] = h;
    g_w[lo] = __float2bfloat16(w - __bfloat162float(h));
}

__global__ void prep_weights(const float* __restrict__ dw1, const float* __restrict__ db1,
                             const float* __restrict__ dw2, const float* __restrict__ db2,
                             const float* __restrict__ rw1, const float* __restrict__ rb1,
                             const float* __restrict__ rw2, const float* __restrict__ rb2)
{
    const int tid = threadIdx.x;
    for (int i = tid; i < W_ELEMS; i += 256) g_w[i] = __float2bfloat16(0.0f);
    __syncthreads();
    // W1t[n][k]: k<47 = dw1[k][n]; k=47 = db1[n]  (A col47 == 1)
    for (int i = tid; i < 64 * 48; i += 256) {
        int nn = i / 48, k = i % 48;
        float w = (k < 47) ? dw1[k * 64 + nn] : db1[nn];
        put_w(oW1h + nn * sW1 + k, oW1l + nn * sW1 + k, w);
    }
    // W2t[n][k]: n<64 = dw2[k][n+1] (feat perm); n=64 = dw2[k][0] (sigma)
    for (int i = tid; i < 65 * 64; i += 256) {
        int nn = i / 64, k = i % 64;
        float w = (nn < 64) ? dw2[k * 65 + nn + 1] : dw2[k * 65];
        put_w(oW2h + nn * sW2 + k, oW2l + nn * sW2 + k, w);
    }
    // W3t[n][k]: k<73 = rw1[k][n]; k=73 = rb1[n]  (A3 col73 == 1)
    for (int i = tid; i < 64 * 74; i += 256) {
        int nn = i / 74, k = i % 74;
        float w = (k < 73) ? rw1[k * 64 + nn] : rb1[nn];
        put_w(oW3h + nn * sW3 + k, oW3l + nn * sW3 + k, w);
    }
    // W4t[n][k]: n<3 = rw2[k][n]
    for (int i = tid; i < 3 * 64; i += 256) {
        int nn = i / 64, k = i % 64;
        put_w(oW4h + nn * sW4 + k, oW4l + nn * sW4 + k, rw2[k * 3 + nn]);
    }
    if (tid < 72) g_b2[tid] = (tid < 64) ? db2[tid + 1] : ((tid == 64) ? db2[0] : 0.0f);
    if (tid < 8)  g_b4[tid] = (tid < 3) ? rb2[tid] : 0.0f;
}

// ---------------- staging store (bf16 hi/lo, stride 72 elems = 144B) ----------------
__device__ __forceinline__ void put_st(__nv_bfloat16* H, __nv_bfloat16* L,
                                       int r, int c, float w) {
    __nv_bfloat16 h = __float2bfloat16(w);
    H[r * 72 + c] = h;
    L[r * 72 + c] = __float2bfloat16(w - __bfloat162float(h));
}

__device__ __forceinline__ float sigmoidf_(float z) {
    return 1.0f / (1.0f + __expf(-z));
}

// ---------------- main kernel ----------------
__global__ void __launch_bounds__(256, 2) nerf_mma2(
    const float* __restrict__ x, const float* __restrict__ v,
    const float* __restrict__ table, float* __restrict__ out, int n)
{
    extern __shared__ __align__(16) unsigned char S[];
    const int tid = threadIdx.x, wid = tid >> 5, lane = tid & 31;

    // stage weights + biases into smem
    for (int i = tid; i < 59904 / 16; i += 256)
        ((uint4*)S)[i] = ((const uint4*)g_w)[i];
    float* sB2 = (float*)(S + oSB2B);
    float* sB4 = (float*)(S + oSB4B);
    if (tid < 72) sB2[tid] = g_b2[tid];
    if (tid < 8)  sB4[tid] = g_b4[tid];
    __syncthreads();

    const uint32_t uS = smem_u32(S);
    const int g = lane >> 2, t2 = (lane & 3) * 2;
    const int row = lane >> 1, half = lane & 1;

    __nv_bfloat16* stH = (__nv_bfloat16*)(S + oSTB + wid * 4608);
    __nv_bfloat16* stL = stH + 1152;
    const uint32_t uStH = uS + oSTB + wid * 4608;
    const uint32_t uStL = uStH + 2304;

    // ldmatrix lane-offset patterns
    const uint32_t aofs   = (lane & 15) * 144 + (lane >> 4) * 16;               // A x4
    const uint32_t bo112  = (lane & 7) * 112 + (lane >> 3) * 16;                // B x4
    const uint32_t bo112b = (lane & 7) * 112 + ((lane >> 3) & 1) * 16;          // B x2
    const uint32_t bo144  = (lane & 7) * 144 + (lane >> 3) * 16;
    const uint32_t bo176  = (lane & 7) * 176 + (lane >> 3) * 16;
    const uint32_t bo176b = (lane & 7) * 176 + ((lane >> 3) & 1) * 16;

    const uint32_t uW1h  = uS + oW1h * 2 + bo112,        uW1l  = uS + oW1l * 2 + bo112;
    const uint32_t uW1hb = uS + oW1h * 2 + 64 + bo112b,  uW1lb = uS + oW1l * 2 + 64 + bo112b;
    const uint32_t uW2h  = uS + oW2h * 2 + bo144,        uW2l  = uS + oW2l * 2 + bo144;
    const uint32_t uW3h  = uS + oW3h * 2 + bo176,        uW3l  = uS + oW3l * 2 + bo176;
    const uint32_t uW3hb = uS + oW3h * 2 + 128 + bo176b, uW3lb = uS + oW3l * 2 + 128 + bo176b;
    const uint32_t uW4h  = uS + oW4h * 2 + bo144,        uW4l  = uS + oW4l * 2 + bo144;

    const int ntiles = n >> 4;
    const int totw = gridDim.x * 8;

    for (int tile = blockIdx.x * 8 + wid; tile < ntiles; tile += totw) {
        const int p = tile * 16 + row;
        const float px0 = x[3 * p], px1 = x[3 * p + 1], px2 = x[3 * p + 2];

        // ---------------- encoding -> staging ----------------
        if (half == 0) {
            put_st(stH, stL, row, 0, px0);
            put_st(stH, stL, row, 1, px1);
            put_st(stH, stL, row, 2, px2);
            const float pv[2] = {px0, px1};
            #pragma unroll
            for (int d = 0; d < 2; d++) {
                float fm = 1.0f;
                #pragma unroll
                for (int fr = 0; fr < 6; fr++) {
                    float s, c;
                    __sincosf(pv[d] * fm, &s, &c);
                    put_st(stH, stL, row, 3 + d * 12 + fr, s);
                    put_st(stH, stL, row, 3 + d * 12 + 6 + fr, c);
                    fm *= 2.0f;
                }
            }
            // SH -> staging cols 48..56; bias-1 at 57; zero 58..63
            const float vx = v[3 * p], vy = v[3 * p + 1], vz = v[3 * p + 2];
            put_st(stH, stL, row, 48, 0.28209479177387814f);
            put_st(stH, stL, row, 49, -0.4886025119029199f * vy);
            put_st(stH, stL, row, 50,  0.4886025119029199f * vz);
            put_st(stH, stL, row, 51, -0.4886025119029199f * vx);
            put_st(stH, stL, row, 52,  1.0925484305920792f * vx * vy);
            put_st(stH, stL, row, 53, -1.0925484305920792f * vy * vz);
            put_st(stH, stL, row, 54,  0.9461746957575601f * vz * vz - 0.31539156525252005f);
            put_st(stH, stL, row, 55, -1.0925484305920792f * vx * vz);
            put_st(stH, stL, row, 56,  0.5462742152960396f * (vx * vx - vy * vy));
            put_st(stH, stL, row, 57, 1.0f);
            #pragma unroll
            for (int q = 58; q < 64; q++) put_st(stH, stL, row, q, 0.0f);
        } else {
            float fm = 1.0f;
            #pragma unroll
            for (int fr = 0; fr < 6; fr++) {
                float s, c;
                __sincosf(px2 * fm, &s, &c);
                put_st(stH, stL, row, 27 + fr, s);
                put_st(stH, stL, row, 33 + fr, c);
                fm *= 2.0f;
            }
            const float x01x = (px0 + 1.0f) * 0.5f;
            const float x01y = (px1 + 1.0f) * 0.5f;
            const float x01z = (px2 + 1.0f) * 0.5f;
            const float resf[4] = {33.0f, 43.0f, 56.0f, 74.0f};
            #pragma unroll
            for (int lv = 0; lv < 4; lv++) {
                const float pxx = x01x * resf[lv], pyy = x01y * resf[lv], pzz = x01z * resf[lv];
                const float fx = floorf(pxx), fy = floorf(pyy), fz = floorf(pzz);
                const float tx = pxx - fx, ty = pyy - fy, tz = pzz - fz;
                const float wx = tx * tx * (3.0f - 2.0f * tx);
                const float wy = ty * ty * (3.0f - 2.0f * ty);
                const float wz = tz * tz * (3.0f - 2.0f * tz);
                const unsigned cx = (unsigned)fx, cy = (unsigned)fy, cz = (unsigned)fz;
                const float* tb = table + (size_t)lv * (TSZ * 2);
                float f0 = 0.0f, f1 = 0.0f;
                #pragma unroll
                for (int c = 0; c < 8; c++) {
                    const unsigned hx = cx + (c & 1);
                    const unsigned hy = cy + ((c >> 1) & 1);
                    const unsigned hz = cz + ((c >> 2) & 1);
                    const unsigned hsh = (hx ^ (hy * 2654435761u) ^ (hz * 805459861u)) & (unsigned)(TSZ - 1);
                    const float cw = ((c & 1) ? wx : 1.0f - wx)
                                   * (((c >> 1) & 1) ? wy : 1.0f - wy)
                                   * (((c >> 2) & 1) ? wz : 1.0f - wz);
                    const float2 tv = __ldg(reinterpret_cast<const float2*>(tb + 2u * hsh));
                    f0 = fmaf(tv.x, cw, f0);
                    f1 = fmaf(tv.y, cw, f1);
                }
                put_st(stH, stL, row, 39 + 2 * lv, f0);
                put_st(stH, stL, row, 40 + 2 * lv, f1);
            }
            put_st(stH, stL, row, 47, 1.0f);  // bias-1 column for L1
        }
        __syncwarp();

        // ---------------- A1 fragments ----------------
        uint32_t a1h[3][4], a1l[3][4];
        ldsm4(a1h[0], uStH + aofs);      ldsm4(a1h[1], uStH + aofs + 32);
        ldsm4(a1h[2], uStH + aofs + 64);
        ldsm4(a1l[0], uStL + aofs);      ldsm4(a1l[1], uStL + aofs + 32);
        ldsm4(a1l[2], uStL + aofs + 64);

        // ---------------- L1 ----------------
        uint32_t a2h[4][4], a2l[4][4];
        #pragma unroll
        for (int m = 0; m < 4; m++) {
            float c[2][4];
            #pragma unroll
            for (int u = 0; u < 2; u++) {
                const uint32_t jb = (2 * m + u) * (8 * 112);
                float* cc = c[u];
                cc[0] = cc[1] = cc[2] = cc[3] = 0.0f;
                pass2(cc, a1h, a1l, 0, uW1h + jb, uW1l + jb);
                pass1(cc, a1h[2], a1l[2], uW1hb + jb, uW1lb + jb);
            }
            a2h[m][0] = bf2r(c[0][0], c[0][1], a2l[m][0]);
            a2h[m][1] = bf2r(c[0][2], c[0][3], a2l[m][1]);
            a2h[m][2] = bf2r(c[1][0], c[1][1], a2l[m][2]);
            a2h[m][3] = bf2r(c[1][2], c[1][3], a2l[m][3]);
        }

        // ---------------- L2 ----------------
        uint32_t a3h[5][4], a3l[5][4];
        #pragma unroll
        for (int m = 0; m < 4; m++) {
            float c[2][4];
            #pragma unroll
            for (int u = 0; u < 2; u++) {
                const int j = 2 * m + u;
                const uint32_t jb = j * (8 * 144);
                float* cc = c[u];
                const float2 bb = *(const float2*)(sB2 + 8 * j + t2);
                cc[0] = bb.x; cc[1] = bb.y; cc[2] = bb.x; cc[3] = bb.y;
                pass2(cc, a2h, a2l, 0, uW2h + jb, uW2l + jb);
                pass2(cc, a2h, a2l, 2, uW2h + jb + 64, uW2l + jb + 64);
            }
            a3h[m][0] = bf2r(c[0][0], c[0][1], a3l[m][0]);
            a3h[m][1] = bf2r(c[0][2], c[0][3], a3l[m][1]);
            a3h[m][2] = bf2r(c[1][0], c[1][1], a3l[m][2]);
            a3h[m][3] = bf2r(c[1][2], c[1][3], a3l[m][3]);
        }
        {   // sigma n-tile (cols 64..71, only col 64 meaningful)
            float cc[4];
            const float2 bb = *(const float2*)(sB2 + 64 + t2);
            cc[0] = bb.x; cc[1] = bb.y; cc[2] = bb.x; cc[3] = bb.y;
            const uint32_t jb = 8 * (8 * 144);
            pass2(cc, a2h, a2l, 0, uW2h + jb, uW2l + jb);
            pass2(cc, a2h, a2l, 2, uW2h + jb + 64, uW2l + jb + 64);
            if ((lane & 3) == 0) {
                out[tile * 16 + g]     = __expf(cc[0]);
                out[tile * 16 + g + 8] = __expf(cc[2]);
            }
        }
        // SH fragment (A3 k-tile 4, staging cols 48..63)
        ldsm4(a3h[4], uStH + aofs + 96);
        ldsm4(a3l[4], uStL + aofs + 96);

        // ---------------- L3 ----------------
        uint32_t a4h[4][4], a4l[4][4];
        #pragma unroll
        for (int m = 0; m < 4; m++) {
            float c[2][4];
            #pragma unroll
            for (int u = 0; u < 2; u++) {
                const uint32_t jb = (2 * m + u) * (8 * 176);
                float* cc = c[u];
                cc[0] = cc[1] = cc[2] = cc[3] = 0.0f;
                pass2(cc, a3h, a3l, 0, uW3h + jb, uW3l + jb);
                pass2(cc, a3h, a3l, 2, uW3h + jb + 64, uW3l + jb + 64);
                pass1(cc, a3h[4], a3l[4], uW3hb + jb, uW3lb + jb);
            }
            a4h[m][0] = bf2r(c[0][0], c[0][1], a4l[m][0]);
            a4h[m][1] = bf2r(c[0][2], c[0][3], a4l[m][1]);
            a4h[m][2] = bf2r(c[1][0], c[1][1], a4l[m][2]);
            a4h[m][3] = bf2r(c[1][2], c[1][3], a4l[m][3]);
        }

        // ---------------- L4 + rgb ----------------
        {
            float cc[4];
            const float2 bb = *(const float2*)(sB4 + t2);
            cc[0] = bb.x; cc[1] = bb.y; cc[2] = bb.x; cc[3] = bb.y;
            pass2(cc, a4h, a4l, 0, uW4h, uW4l);
            pass2(cc, a4h, a4l, 2, uW4h + 64, uW4l + 64);
            const int pg = tile * 16 + g;
            if ((lane & 3) == 0) {
                out[n + 3 * pg + 0]       = sigmoidf_(cc[0]);
                out[n + 3 * pg + 1]       = sigmoidf_(cc[1]);
                out[n + 3 * (pg + 8) + 0] = sigmoidf_(cc[2]);
                out[n + 3 * (pg + 8) + 1] = sigmoidf_(cc[3]);
            } else if ((lane & 3) == 1) {
                out[n + 3 * pg + 2]       = sigmoidf_(cc[0]);
                out[n + 3 * (pg + 8) + 2] = sigmoidf_(cc[2]);
            }
        }
        __syncwarp();
    }
}

extern "C" void kernel_launch(void* const* d_in, const int* in_sizes, int n_in,
                              void* d_out, int out_size)
{
    const float* x     = (const float*)d_in[0];
    const float* v     = (const float*)d_in[1];
    const float* table = (const float*)d_in[3];
    const float* dw1   = (const float*)d_in[4];
    const float* db1   = (const float*)d_in[5];
    const float* dw2   = (const float*)d_in[6];
    const float* db2   = (const float*)d_in[7];
    const float* rw1   = (const float*)d_in[8];
    const float* rb1   = (const float*)d_in[9];
    const float* rw2   = (const float*)d_in[10];
    const float* rb2   = (const float*)d_in[11];
    float* out = (float*)d_out;

    const int n = in_sizes[0] / 3;

    cudaFuncSetAttribute(nerf_mma2, cudaFuncAttributeMaxDynamicSharedMemorySize, SMEM_DYN);

    prep_weights<<<1, 256>>>(dw1, db1, dw2, db2, rw1, rb1, rw2, rb2);
    nerf_mma2<<<296, 256, SMEM_DYN>>>(x, v, table, out, n);
}